// round 5
// baseline (speedup 1.0000x reference)
#include <cuda_runtime.h>

// DTW loss: B=16, C=8, T=512 -> 128 independent 512x512 DTW DPs.
// One block (128 threads / 4 warps) per (b,c) pair. Lane l owns 4 contiguous
// DP columns; at step s it computes row i = s - l + 1 (skewed wavefront).
//
//  - No per-step __syncthreads. Cross-warp carry handoff via sync-free shared
//    array hand[producer_warp][step] (one slot per step, sentinel -1.0f; all
//    DP values >= 0, so consumers spin on v < 0). Poll predicate is
//    warp-uniform -> no divergence. Producer and consumer warps live on
//    different SMSPs (wid%4), so the spin cannot starve the producer.
//  - Lane 0 of warp 0 uses left = BIG (DP column 0 is +inf boundary).
//  - Reduction fused via threadfence + atomic counter (deterministic
//    fixed-order sum by the last-arriving block; counter reset for replay).

#define TT    512
#define BIGF  1e30f
#define HSTEPS (TT + 128)          // 640 slots per producer warp

__device__ float        g_partials[128];
__device__ unsigned int g_counter = 0;

__global__ __launch_bounds__(128, 1)
void dtw_fused_kernel(const float* __restrict__ inputs,
                      const float* __restrict__ targets,
                      float* __restrict__ out) {
    const int p    = blockIdx.x;          // pair index 0..127
    const float* x = inputs  + p * TT;
    const float* y = targets + p * TT;
    const int tid  = threadIdx.x;         // 0..127
    const int lane = tid & 31;
    const int warp = tid >> 5;

    __shared__ float xs[TT];
    __shared__ float hand[3 * HSTEPS];    // producer warps 0..2

    for (int k = tid; k < TT; k += 128) xs[k] = x[k];
    for (int k = tid; k < 3 * HSTEPS; k += 128) hand[k] = -1.0f;

    // This lane's 4 column values of y (DP columns j = 4*tid+1 .. 4*tid+4)
    const float y0 = y[tid * 4 + 0];
    const float y1 = y[tid * 4 + 1];
    const float y2 = y[tid * 4 + 2];
    const float y3 = y[tid * 4 + 3];

    float up0 = BIGF, up1 = BIGF, up2 = BIGF, up3 = BIGF;
    float carry     = BIGF;               // v of last owned column, prev step
    float left_prev = BIGF;               // left received in previous step

    __syncthreads();                      // xs + sentinel init visible

    volatile float* const poll_slot = hand + (warp - 1) * HSTEPS;  // consumer
    volatile float* const push_slot = hand + warp * HSTEPS;        // producer

    const int S = TT + 127;               // 639 wavefront steps
    int i = 1 - tid;                      // DP row computed this step

    for (int s = 0; s < S; ++s, ++i) {
        // left(i, j0) = dtw[i][j0-1], produced by lane-1 in the previous step.
        float left = __shfl_up_sync(0xffffffffu, carry, 1);

        if (warp == 0) {
            // DP column 0 is the +inf boundary for lane 0's left neighbor.
            if (lane == 0) left = BIGF;
        } else if ((unsigned)(s - warp * 32) < (unsigned)TT) {
            // Cross-warp handoff for lane 0. Predicate is warp-uniform:
            // lane 0 of warp w is active exactly for s in [32w, 32w + TT - 1].
            float v = poll_slot[s - 1];             // broadcast LDS
            while (v < 0.0f) { v = poll_slot[s - 1]; }
            if (lane == 0) left = v;
        }

        if ((unsigned)(i - 1) < (unsigned)TT) {   // 1 <= i <= TT
            // diag of first owned column = dtw[i-1][j0-1]
            const float diag0 = (i == 1) ? ((tid == 0) ? 0.0f : BIGF) : left_prev;
            const float xi = xs[i - 1];

            const float d0 = xi - y0;
            const float d1 = xi - y1;
            const float d2 = xi - y2;
            const float d3 = xi - y3;
            const float m0 = fminf(up0, diag0);
            const float m1 = fminf(up1, up0);     // diag of col k (k>0) = up[k-1]
            const float m2 = fminf(up2, up1);
            const float m3 = fminf(up3, up2);

            // Critical chain: 4 x (FMNMX + FADD) -- |d| folds in as input-abs.
            const float v0 = fabsf(d0) + fminf(left, m0);
            const float v1 = fabsf(d1) + fminf(v0,   m1);
            const float v2 = fabsf(d2) + fminf(v1,   m2);
            const float v3 = fabsf(d3) + fminf(v2,   m3);

            up0 = v0; up1 = v1; up2 = v2; up3 = v3;
            carry     = v3;
            left_prev = left;
        }

        // Publish this step's carry for the next warp (unconditional, so
        // consumers' polls always terminate even in fill/drain regions).
        if (lane == 31 && warp < 3) push_slot[s] = carry;
    }

    // Lane 127 holds dtw[T][T] after the last step.
    if (tid == 127) {
        g_partials[p] = carry * (1.0f / (float)TT);
        __threadfence();
        unsigned int old = atomicAdd(&g_counter, 1u);
        if (old == 127u) {
            // Last block: all other partials are L2-visible (fenced before
            // their atomics). Fixed-order sum -> deterministic.
            volatile float* gp = g_partials;
            float sum = 0.0f;
            #pragma unroll 16
            for (int k = 0; k < 128; ++k) sum += gp[k];
            out[0] = sum * 0.125f;        // mean over C=8, sum over B
            *(volatile unsigned int*)&g_counter = 0;  // reset for next replay
        }
    }
}

extern "C" void kernel_launch(void* const* d_in, const int* in_sizes, int n_in,
                              void* d_out, int out_size) {
    const float* inputs  = (const float*)d_in[0];
    const float* targets = (const float*)d_in[1];
    float* out = (float*)d_out;
    (void)in_sizes; (void)n_in; (void)out_size;

    dtw_fused_kernel<<<128, 128>>>(inputs, targets, out);
}

// round 6
// speedup vs baseline: 1.2522x; 1.2522x over previous
#include <cuda_runtime.h>

// DTW loss: B=16, C=8, T=512 -> 128 independent 512x512 DTW DPs.
// One block (128 threads / 4 warps) per pair. Lane l owns 4 DP columns.
// Skewed wavefront: lane (l, warp w) computes row i = s - sigma + 1 at step s,
//   sigma = 2*l + 66*w  (intra-warp skew 2, inter-warp skew 4).
// - Intra-warp skew 2 hides the SHFL (26 cyc): shfl for step s+1 issues at s.
// - Inter-warp skew 4 (~150 cyc slack) >> STS->LDS visibility: the handoff
//   slot is PREFETCHED one step early; the sentinel check is a never-taken
//   uniform branch. (R5 used skew 1 => chronic poll misses => 300 cyc/step.)
// - xs value prefetched one step ahead (hides LDS latency/conflicts).
// - Fused deterministic reduction via threadfence + atomic counter.

#define TT     512
#define MAXSK  260                  // sigma(lane31,warp3) = 62 + 198
#define NSTEP  (TT + MAXSK)         // 772 wavefront steps
#define BIGF   1e30f

__device__ float        g_partials[128];
__device__ unsigned int g_counter = 0;

__global__ __launch_bounds__(128, 1)
void dtw_fused_kernel(const float* __restrict__ inputs,
                      const float* __restrict__ targets,
                      float* __restrict__ out) {
    const int p    = blockIdx.x;
    const float* x = inputs  + p * TT;
    const float* y = targets + p * TT;
    const int tid  = threadIdx.x;
    const int lane = tid & 31;
    const int warp = tid >> 5;
    const int sigma = 2 * lane + 66 * warp;

    // xs padded on both sides so prefetch index s+1-sigma never needs clamping.
    __shared__ float xsbuf[MAXSK + TT + MAXSK + 4];
    // hand: 4-float guard prefix so prefetch index s-3 (>= -3) stays in-bounds.
    __shared__ float handbuf[4 + 3 * NSTEP];

    float* const xsp = xsbuf + MAXSK;            // xsp[0..TT-1] = x
    for (int k = tid; k < TT; k += 128) xsp[k] = x[k];
    for (int k = tid; k < 4 + 3 * NSTEP; k += 128) handbuf[k] = -1.0f;

    const float y0 = y[tid * 4 + 0];
    const float y1 = y[tid * 4 + 1];
    const float y2 = y[tid * 4 + 2];
    const float y3 = y[tid * 4 + 3];
    const float d1v = (tid == 0) ? 0.0f : BIGF;  // diag for row 1 (dtw[0][j0-1])

    float up0 = BIGF, up1 = BIGF, up2 = BIGF, up3 = BIGF;
    float carry = BIGF;          // carry(s-1) entering step s
    float left_prev = BIGF;      // left used in previous valid row (-> diag)
    float left_use = BIGF;       // lane l-1 carry(s-2), shfl'd during step s-1
    float hand_use = BIGF;       // slot[s-4], prefetched during step s-1

    __syncthreads();             // xs + sentinels visible to all warps

    float xv = xsp[-sigma < 0 ? 0 : -sigma];     // row value for step 0
    // (only lane0/warp0 has a valid row at s=0; its index is 0)

    float*          const poll  = handbuf + 4 + (warp - 1) * NSTEP;
    volatile float* const vpoll = poll;
    volatile float* const vpush = handbuf + 4 + warp * NSTEP;

    const bool is_cons = (warp > 0);
    const bool is_prod = (lane == 31 && warp < 3);
    const int  wlo     = 66 * warp;              // consumer lane0 valid window

    #pragma unroll 2
    for (int s = 0; s < NSTEP; ++s) {
        // ---- prefetches for step s+1 (all off the critical chain) ----
        const float left_next = __shfl_up_sync(0xffffffffu, carry, 1);
        const float hand_next = is_cons ? poll[s - 3] : BIGF;   // guard covers s<3
        const float xv_next   = xsp[s + 1 - sigma];             // pad covers range

        // ---- resolve this step's handoff (never-taken check in steady state) ----
        if (is_cons && (unsigned)(s - wlo) < (unsigned)TT) {
            float h = hand_use;
            while (h < 0.0f) h = vpoll[s - 4];   // rare: slack = 4 steps
            hand_use = h;
        }

        // ---- DP row update ----
        const unsigned r = (unsigned)(s - sigma);               // i-1
        if (r < (unsigned)TT) {
            float left = left_use;
            if (lane == 0) left = (warp == 0) ? BIGF : hand_use;
            const float diag0 = (r == 0) ? d1v : left_prev;
            const float m0 = fminf(up0, diag0);
            const float m1 = fminf(up1, up0);
            const float m2 = fminf(up2, up1);
            const float m3 = fminf(up3, up2);
            const float v0 = fabsf(xv - y0) + fminf(left, m0);
            const float v1 = fabsf(xv - y1) + fminf(v0,   m1);
            const float v2 = fabsf(xv - y2) + fminf(v1,   m2);
            const float v3 = fabsf(xv - y3) + fminf(v2,   m3);
            up0 = v0; up1 = v1; up2 = v2; up3 = v3;
            left_prev = left;
            carry = v3;
        }

        // ---- publish carry(s) for the next warp (unconditional per step) ----
        if (is_prod) vpush[s] = carry;

        left_use = left_next;
        hand_use = hand_next;
        xv       = xv_next;
    }

    // Lane 127: carry = dtw[T][T] (row 512 computed at step NSTEP-1).
    if (tid == 127) {
        g_partials[p] = carry * (1.0f / (float)TT);
        __threadfence();
        unsigned int old = atomicAdd(&g_counter, 1u);
        if (old == 127u) {
            volatile float* gp = g_partials;
            float sum = 0.0f;
            #pragma unroll 16
            for (int k = 0; k < 128; ++k) sum += gp[k];
            out[0] = sum * 0.125f;       // mean over C=8, sum over B
            *(volatile unsigned int*)&g_counter = 0;   // reset for replay
        }
    }
}

extern "C" void kernel_launch(void* const* d_in, const int* in_sizes, int n_in,
                              void* d_out, int out_size) {
    const float* inputs  = (const float*)d_in[0];
    const float* targets = (const float*)d_in[1];
    float* out = (float*)d_out;
    (void)in_sizes; (void)n_in; (void)out_size;

    dtw_fused_kernel<<<128, 128>>>(inputs, targets, out);
}

// round 7
// speedup vs baseline: 1.7773x; 1.4193x over previous
#include <cuda_runtime.h>

// DTW loss: B=16, C=8, T=512 -> 128 independent 512x512 DTW DPs.
// One block (128 threads / 4 warps) per pair; lane l owns 4 DP columns.
// Skewed wavefront: lane (l, w) computes row i = s - sigma + 1, sigma = 2l + 66w.
//   intra-warp skew 2 -> SHFL (26cy) prefetched a full step ahead, off-chain.
//   inter-warp skew 4 -> handoff slot prefetched a step ahead; sentinel check
//   is a never-taken uniform branch (4 steps of jitter tolerance).
// R7: BRANCHLESS steady state. DP update runs unconditionally:
//   fill:  left/diag = BIG selects => v = cost + 1e30 == 1e30 exactly, so
//          up-registers remain bit-exact BIG until the lane's first real row.
//   drain: garbage is provably never consumed (slot boundary = producer's
//          last valid step; lane 127 never drains; x pad zero-filled).
// Publish is a single predicated STS; poll spin is the only BSSY region.

#define TT     512
#define MAXSK  260                  // sigma(lane31, warp3)
#define NSTEP  (TT + MAXSK)         // 772 steps (divisible by 4)
#define BIGF   1e30f

__device__ float        g_partials[128];
__device__ unsigned int g_counter = 0;

__global__ __launch_bounds__(128, 1)
void dtw_fused_kernel(const float* __restrict__ inputs,
                      const float* __restrict__ targets,
                      float* __restrict__ out) {
    const int p    = blockIdx.x;
    const float* x = inputs  + p * TT;
    const float* y = targets + p * TT;
    const int tid  = threadIdx.x;
    const int lane = tid & 31;
    const int warp = tid >> 5;
    const int sigma = 2 * lane + 66 * warp;

    __shared__ float xsbuf[MAXSK + TT + MAXSK + 8];   // zero-padded both sides
    __shared__ float handbuf[4 + 3 * NSTEP];          // 4-slot guard prefix

    float* const xsp = xsbuf + MAXSK;
    // Zero pads and x region disjointly (no sync needed between them).
    for (int k = tid; k < MAXSK; k += 128)      xsbuf[k] = 0.0f;
    for (int k = tid; k < MAXSK + 8; k += 128)  xsbuf[MAXSK + TT + k] = 0.0f;
    for (int k = tid; k < TT; k += 128)         xsp[k] = x[k];
    for (int k = tid; k < 4 + 3 * NSTEP; k += 128) handbuf[k] = -1.0f;

    const float y0 = y[tid * 4 + 0];
    const float y1 = y[tid * 4 + 1];
    const float y2 = y[tid * 4 + 2];
    const float y3 = y[tid * 4 + 3];
    const float d1v = (tid == 0) ? 0.0f : BIGF;   // diag for row 1

    float up0 = BIGF, up1 = BIGF, up2 = BIGF, up3 = BIGF;
    float carry = BIGF, left_prev = BIGF;
    float left_use = BIGF;      // lane l-1 carry(s-2), shfl'd during step s-1
    float hand_use = BIGF;      // slot[s-4], prefetched during step s-1

    __syncthreads();

    float xv = xsp[-sigma];     // pad covers -260..-1; lane0/warp0 gets x[0]

    // warp 0 never consumes; point its poll base at its own push region
    // (in-bounds, values ignored) so the prefetch LDS is unconditional.
    float*          const poll  = handbuf + 4 + (warp > 0 ? (warp - 1) * NSTEP : 0);
    volatile float* const vpoll = poll;
    volatile float* const vpush = handbuf + 4 + warp * NSTEP;

    const bool is_cons = (warp > 0);
    const bool is_prod = (lane == 31 && warp < 3);
    const int  wlo     = 66 * warp;

    #pragma unroll 4
    for (int s = 0; s < NSTEP; ++s) {
        // Prefetches for step s+1 (issued before carry is overwritten).
        const float left_next = __shfl_up_sync(0xffffffffu, carry, 1); // carry(s-1)
        const float hand_next = poll[s - 3];          // guard prefix covers s<3
        const float xv_next   = xsp[s + 1 - sigma];   // pads cover full range

        // This step's handoff. Warp-uniform predicate; never taken in
        // steady state (prefetch already valid). Spin re-reads slot s-4.
        const bool in_win = is_cons && ((unsigned)(s - wlo) < (unsigned)TT);
        if (in_win && hand_use < 0.0f) {
            float h;
            do { h = vpoll[s - 4]; } while (h < 0.0f);
            hand_use = h;
        }

        // Branchless DP update (valid rows compute real values; fill keeps
        // up == BIG exactly; drain garbage is never consumed).
        float left = left_use;
        if (lane == 0) left = in_win ? hand_use : BIGF;   // predicated select

        const unsigned r = (unsigned)(s - sigma);
        const float diag0 = (r == 0u) ? d1v : left_prev;  // select
        const float m0 = fminf(up0, diag0);
        const float m1 = fminf(up1, up0);
        const float m2 = fminf(up2, up1);
        const float m3 = fminf(up3, up2);
        const float v0 = fabsf(xv - y0) + fminf(left, m0);
        const float v1 = fabsf(xv - y1) + fminf(v0,   m1);
        const float v2 = fabsf(xv - y2) + fminf(v1,   m2);
        const float v3 = fabsf(xv - y3) + fminf(v2,   m3);
        up0 = v0; up1 = v1; up2 = v2; up3 = v3;
        left_prev = left;
        carry = v3;

        if (is_prod) vpush[s] = carry;   // single predicated STS

        left_use = left_next;
        hand_use = hand_next;
        xv       = xv_next;
    }

    // tid 127 (sigma = 260) computes row 512 at the last step: carry = dtw[T][T].
    if (tid == 127) {
        g_partials[p] = carry * (1.0f / (float)TT);
        __threadfence();
        unsigned int old = atomicAdd(&g_counter, 1u);
        if (old == 127u) {
            volatile float* gp = g_partials;
            float sum = 0.0f;
            #pragma unroll 16
            for (int k = 0; k < 128; ++k) sum += gp[k];
            out[0] = sum * 0.125f;                       // (1/C)*sum_b
            *(volatile unsigned int*)&g_counter = 0;     // reset for replay
        }
    }
}

extern "C" void kernel_launch(void* const* d_in, const int* in_sizes, int n_in,
                              void* d_out, int out_size) {
    const float* inputs  = (const float*)d_in[0];
    const float* targets = (const float*)d_in[1];
    float* out = (float*)d_out;
    (void)in_sizes; (void)n_in; (void)out_size;

    dtw_fused_kernel<<<128, 128>>>(inputs, targets, out);
}

// round 8
// speedup vs baseline: 2.6675x; 1.5009x over previous
#include <cuda_runtime.h>

// DTW loss: B=16, C=8, T=512 -> 128 independent 512x512 DTW DPs.
// One block (128 threads / 4 warps) per pair; lane l owns 4 DP columns
// (j = 4*tid+1 .. 4*tid+4). SUPERSTEP design: each superstep computes a
// 4-row x 4-col block (16 cells), so all fixed overhead (shfl, handoff,
// predicates, loop) is amortized over 4 rows.
//   sigma(tid) = lane + 34*warp  (supersteps; intra-warp skew 1, inter 34)
//   lane l at superstep t computes rows 4*(t-sigma)+1 .. +4.
// - Intra-warp: 4 SHFLs at top of body read lane l-1's carries from the
//   previous superstep (warp lockstep => exact, no timing risk).
// - Inter-warp: one STS.128/LDS.128 float4 slot per superstep, write-once,
//   sentinel -1, prefetched 1 superstep early; slack = 3 supersteps so the
//   spin branch is never taken in steady state.
// - Branchless fill/drain: skew algebra delivers BIG lefts exactly until a
//   lane's first valid superstep (1e30 + c == 1e30 in fp32); drain garbage
//   is never consumed (consumer's last slot == producer's last valid).
// - Fused deterministic reduction (threadfence + atomic counter).

#define TT     512
#define IWS    34                    // inter-warp skew in supersteps
#define SIGMX  (31 + 3 * IWS)        // 133
#define NS     (TT / 4 + SIGMX)      // 261 supersteps
#define BIGF   1e30f

__device__ float        g_partials[128];
__device__ unsigned int g_counter = 0;

__global__ __launch_bounds__(128, 1)
void dtw_fused_kernel(const float* __restrict__ inputs,
                      const float* __restrict__ targets,
                      float* __restrict__ out) {
    const int p    = blockIdx.x;
    const float* x = inputs  + p * TT;
    const int tid  = threadIdx.x;
    const int lane = tid & 31;
    const int warp = tid >> 5;
    const int sig  = lane + IWS * warp;

    // x rows, float4-per-superstep, padded so index t+1-sig in [-133, 261]
    __shared__ float4 xsbuf[SIGMX + TT / 4 + SIGMX + 1];   // 395 float4
    // handoff slots: 3-slot guard prefix (sentinel) + 3 producer regions
    __shared__ float4 handbuf[3 + 3 * NS];                 // 786 float4

    float4* const xsp = xsbuf + SIGMX;

    {   // init smem: zero pads, x in the middle, sentinels in handbuf
        float* xf = (float*)xsbuf;
        const int XTOT = (SIGMX + TT / 4 + SIGMX + 1) * 4;
        for (int k = tid; k < SIGMX * 4; k += 128)            xf[k] = 0.0f;
        for (int k = tid; k < (SIGMX + 1) * 4; k += 128)      xf[(SIGMX * 4 + TT) + k] = 0.0f;
        for (int k = tid; k < TT; k += 128)                   xf[SIGMX * 4 + k] = x[k];
        float* hf = (float*)handbuf;
        for (int k = tid; k < (3 + 3 * NS) * 4; k += 128)     hf[k] = -1.0f;
        (void)XTOT;
    }

    const float4 yq = ((const float4*)(targets + p * TT))[tid];
    const float y0 = yq.x, y1 = yq.y, y2 = yq.z, y3 = yq.w;

    float up0 = BIGF, up1 = BIGF, up2 = BIGF, up3 = BIGF;
    float lprev = (tid == 0) ? 0.0f : BIGF;   // diag for a lane's first row
    float c0 = BIGF, c1 = BIGF, c2 = BIGF, c3 = BIGF;   // published carries

    __syncthreads();

    const bool cons = (warp > 0);
    const bool prod = (lane == 31 && warp < 3);
    // warp 0 polls its own push region (values ignored; keeps LDS in-bounds)
    float4* const poll = handbuf + 3 + (cons ? (warp - 1) : warp) * NS;
    float4* const push = handbuf + 3 + warp * NS;
    const int wlo = IWS * warp;

    float4 xq = xsp[-sig];        // rows for superstep 0
    float4 hq = poll[-3];         // slot used at t=0 (guard; checked only in-window)

    for (int t = 0; t < NS; ++t) {
        // Previous superstep's carries from lane l-1 (lockstep-exact).
        float L0 = __shfl_up_sync(0xffffffffu, c0, 1);
        float L1 = __shfl_up_sync(0xffffffffu, c1, 1);
        float L2 = __shfl_up_sync(0xffffffffu, c2, 1);
        float L3 = __shfl_up_sync(0xffffffffu, c3, 1);

        // Prefetches for superstep t+1 (>= 1 superstep of latency slack).
        const float4 xq_n = xsp[t + 1 - sig];
        const float4 hq_n = poll[t - 2];          // slot (t+1)-3

        const bool in_win = cons && ((unsigned)(t - wlo) < (unsigned)(TT / 4));
        if (in_win && hq.w < 0.0f) {              // cold path: ~never taken
            volatile float* vp = (volatile float*)(poll + (t - 3));
            float w;
            do { w = vp[3]; } while (w < 0.0f);
            hq.x = vp[0]; hq.y = vp[1]; hq.z = vp[2]; hq.w = w;
        }

        if (lane == 0) {                          // predicated selects
            L0 = in_win ? hq.x : BIGF;
            L1 = in_win ? hq.y : BIGF;
            L2 = in_win ? hq.z : BIGF;
            L3 = in_win ? hq.w : BIGF;
        }

        // 4x4 DP block. Row r cols j0..j0+3; diag(col0,row r) = left(row r-1).
        float m;
        m = fminf(up0, lprev);  const float v00 = fabsf(xq.x - y0) + fminf(L0,  m);
        m = fminf(up1, up0 );   const float v01 = fabsf(xq.x - y1) + fminf(v00, m);
        m = fminf(up2, up1 );   const float v02 = fabsf(xq.x - y2) + fminf(v01, m);
        m = fminf(up3, up2 );   const float v03 = fabsf(xq.x - y3) + fminf(v02, m);

        m = fminf(v00, L0);     const float v10 = fabsf(xq.y - y0) + fminf(L1,  m);
        m = fminf(v01, v00);    const float v11 = fabsf(xq.y - y1) + fminf(v10, m);
        m = fminf(v02, v01);    const float v12 = fabsf(xq.y - y2) + fminf(v11, m);
        m = fminf(v03, v02);    const float v13 = fabsf(xq.y - y3) + fminf(v12, m);

        m = fminf(v10, L1);     const float v20 = fabsf(xq.z - y0) + fminf(L2,  m);
        m = fminf(v11, v10);    const float v21 = fabsf(xq.z - y1) + fminf(v20, m);
        m = fminf(v12, v11);    const float v22 = fabsf(xq.z - y2) + fminf(v21, m);
        m = fminf(v13, v12);    const float v23 = fabsf(xq.z - y3) + fminf(v22, m);

        m = fminf(v20, L2);     const float v30 = fabsf(xq.w - y0) + fminf(L3,  m);
        m = fminf(v21, v20);    const float v31 = fabsf(xq.w - y1) + fminf(v30, m);
        m = fminf(v22, v21);    const float v32 = fabsf(xq.w - y2) + fminf(v31, m);
        m = fminf(v23, v22);    const float v33 = fabsf(xq.w - y3) + fminf(v32, m);

        up0 = v30; up1 = v31; up2 = v32; up3 = v33;
        lprev = L3;
        c0 = v03; c1 = v13; c2 = v23; c3 = v33;

        if (prod) push[t] = make_float4(c0, c1, c2, c3);   // @P STS.128

        xq = xq_n;
        hq = hq_n;
    }

    // tid 127 (sig=133): last valid superstep is t = NS-1; c3 = dtw[T][T].
    if (tid == 127) {
        g_partials[p] = c3 * (1.0f / (float)TT);
        __threadfence();
        unsigned int old = atomicAdd(&g_counter, 1u);
        if (old == 127u) {
            volatile float* gp = g_partials;
            float sum = 0.0f;
            #pragma unroll 16
            for (int k = 0; k < 128; ++k) sum += gp[k];
            out[0] = sum * 0.125f;                     // (1/C) * sum_b
            *(volatile unsigned int*)&g_counter = 0;   // reset for replay
        }
    }
}

extern "C" void kernel_launch(void* const* d_in, const int* in_sizes, int n_in,
                              void* d_out, int out_size) {
    const float* inputs  = (const float*)d_in[0];
    const float* targets = (const float*)d_in[1];
    float* out = (float*)d_out;
    (void)in_sizes; (void)n_in; (void)out_size;

    dtw_fused_kernel<<<128, 128>>>(inputs, targets, out);
}

// round 9
// speedup vs baseline: 3.0010x; 1.1250x over previous
#include <cuda_runtime.h>

// DTW loss: B=16, C=8, T=512 -> 128 independent 512x512 DTW DPs.
// One block (128 threads / 4 warps) per pair; lane l owns 4 DP columns.
// Superstep = 4 rows x 4 cols per lane. sigma = lane + 33*warp.
// R9: BIG-fill handoff (no in_win selects/predicates: fill carries are
//     bit-exact BIG, guards BIG, warp0 polls a frozen BIG slot; drain
//     garbage >= 0 and never consumed), running-pointer addressing,
//     IWS 34->33, unroll 2. Spin guard is just hq.w < 0 (cold, ~never).

#define TT     512
#define IWS    33
#define SIGMX  (31 + 3 * IWS)        // 130
#define NSS    (TT / 4 + SIGMX)      // 258 supersteps (even)
#define REG    (NSS + 2)             // handoff region: 2 guard + NSS slots
#define BIGF   1e30f

__device__ float        g_partials[128];
__device__ unsigned int g_counter = 0;

__global__ __launch_bounds__(128, 1)
void dtw_fused_kernel(const float* __restrict__ inputs,
                      const float* __restrict__ targets,
                      float* __restrict__ out) {
    const int p    = blockIdx.x;
    const float* x = inputs  + p * TT;
    const int tid  = threadIdx.x;
    const int lane = tid & 31;
    const int warp = tid >> 5;
    const int sig  = lane + IWS * warp;

    // x rows as float4/superstep, pad SIGMX before and SIGMX+2 after (zeros)
    __shared__ float4 xsbuf[SIGMX + TT / 4 + SIGMX + 2];   // 390 float4
    __shared__ float4 handbuf[3 * REG];                    // 780 float4

    float4* const xsp = xsbuf + SIGMX;

    {   // --- init smem ---
        float* xf = (float*)xsbuf;
        const int PRE = SIGMX * 4;                 // 520 floats
        const int POST = (SIGMX + 2) * 4;          // 528 floats
        for (int k = tid; k < PRE; k += 128)        xf[k] = 0.0f;
        for (int k = tid; k < POST; k += 128)       xf[PRE + TT + k] = 0.0f;
        for (int k = tid; k < TT; k += 128)         xf[PRE + k] = x[k];
        float* hf = (float*)handbuf;
        for (int k = tid; k < 3 * REG * 4; k += 128) hf[k] = -1.0f;
    }
    __syncthreads();
    // guards (logical slots -2,-1 of each region) = BIG, after sentinel pass
    if (tid < 24) ((float*)handbuf)[(tid / 8) * REG * 4 + (tid & 7)] = BIGF;

    const float4 yq = ((const float4*)(targets + p * TT))[tid];
    const float y0 = yq.x, y1 = yq.y, y2 = yq.z, y3 = yq.w;

    float up0 = BIGF, up1 = BIGF, up2 = BIGF, up3 = BIGF;
    float lprev = (tid == 0) ? 0.0f : BIGF;        // diag before first row
    float c0 = BIGF, c1 = BIGF, c2 = BIGF, c3 = BIGF;

    const bool prod = (lane == 31 && warp < 3);
    // consumer poll pointer: starts at logical slot -2 (first guard) of the
    // previous warp's region; warp 0 freezes on region0's guard (always BIG).
    float4* pp  = handbuf + (warp > 0 ? (warp - 1) * REG : 0);
    const int pinc = (warp > 0) ? 1 : 0;
    float4* qq  = handbuf + warp * REG + 2;        // push slot t=0
    const float4* xp = xsp - sig;                  // xq for t=0

    __syncthreads();                               // guards + x visible

    float4 xq = xp[0];
    float4 hq = *pp;                               // slot -2 guard = BIG

    #pragma unroll 2
    for (int t = 0; t < NSS; ++t) {
        // lane l-1's previous-superstep carries (lockstep-exact)
        float L0 = __shfl_up_sync(0xffffffffu, c0, 1);
        float L1 = __shfl_up_sync(0xffffffffu, c1, 1);
        float L2 = __shfl_up_sync(0xffffffffu, c2, 1);
        float L3 = __shfl_up_sync(0xffffffffu, c3, 1);

        // prefetches for t+1 (running pointers; 1+ superstep of slack)
        const float4 xq_n = xp[1];
        float4* const pp_n = pp + pinc;
        const float4 hq_n = *pp_n;

        // cold spin: only if the in-window slot is still sentinel
        if (hq.w < 0.0f) {
            volatile float* vp = (volatile float*)pp;
            float w;
            do { w = vp[3]; } while (w < 0.0f);
            hq.x = vp[0]; hq.y = vp[1]; hq.z = vp[2]; hq.w = w;
        }

        // lane0 takes the cross-warp (or boundary-BIG) left values
        if (lane == 0) { L0 = hq.x; L1 = hq.y; L2 = hq.z; L3 = hq.w; }

        // 4x4 DP block
        float m;
        m = fminf(up0, lprev);  const float v00 = fabsf(xq.x - y0) + fminf(L0,  m);
        m = fminf(up1, up0 );   const float v01 = fabsf(xq.x - y1) + fminf(v00, m);
        m = fminf(up2, up1 );   const float v02 = fabsf(xq.x - y2) + fminf(v01, m);
        m = fminf(up3, up2 );   const float v03 = fabsf(xq.x - y3) + fminf(v02, m);

        m = fminf(v00, L0);     const float v10 = fabsf(xq.y - y0) + fminf(L1,  m);
        m = fminf(v01, v00);    const float v11 = fabsf(xq.y - y1) + fminf(v10, m);
        m = fminf(v02, v01);    const float v12 = fabsf(xq.y - y2) + fminf(v11, m);
        m = fminf(v03, v02);    const float v13 = fabsf(xq.y - y3) + fminf(v12, m);

        m = fminf(v10, L1);     const float v20 = fabsf(xq.z - y0) + fminf(L2,  m);
        m = fminf(v11, v10);    const float v21 = fabsf(xq.z - y1) + fminf(v20, m);
        m = fminf(v12, v11);    const float v22 = fabsf(xq.z - y2) + fminf(v21, m);
        m = fminf(v13, v12);    const float v23 = fabsf(xq.z - y3) + fminf(v22, m);

        m = fminf(v20, L2);     const float v30 = fabsf(xq.w - y0) + fminf(L3,  m);
        m = fminf(v21, v20);    const float v31 = fabsf(xq.w - y1) + fminf(v30, m);
        m = fminf(v22, v21);    const float v32 = fabsf(xq.w - y2) + fminf(v31, m);
        m = fminf(v23, v22);    const float v33 = fabsf(xq.w - y3) + fminf(v32, m);

        up0 = v30; up1 = v31; up2 = v32; up3 = v33;
        lprev = L3;
        c0 = v03; c1 = v13; c2 = v23; c3 = v33;

        if (prod) *qq = make_float4(c0, c1, c2, c3);   // @P STS.128

        ++qq; ++xp;
        pp = pp_n;
        xq = xq_n;
        hq = hq_n;
    }

    // tid 127 (sig = 130): last valid superstep is NSS-1; c3 = dtw[T][T].
    if (tid == 127) {
        g_partials[p] = c3 * (1.0f / (float)TT);
        __threadfence();
        unsigned int old = atomicAdd(&g_counter, 1u);
        if (old == 127u) {
            volatile float* gp = g_partials;
            float sum = 0.0f;
            #pragma unroll 16
            for (int k = 0; k < 128; ++k) sum += gp[k];
            out[0] = sum * 0.125f;                     // (1/C) * sum_b
            *(volatile unsigned int*)&g_counter = 0;   // reset for replay
        }
    }
}

extern "C" void kernel_launch(void* const* d_in, const int* in_sizes, int n_in,
                              void* d_out, int out_size) {
    const float* inputs  = (const float*)d_in[0];
    const float* targets = (const float*)d_in[1];
    float* out = (float*)d_out;
    (void)in_sizes; (void)n_in; (void)out_size;

    dtw_fused_kernel<<<128, 128>>>(inputs, targets, out);
}

// round 11
// speedup vs baseline: 3.2111x; 1.0700x over previous
#include <cuda_runtime.h>

// DTW loss: B=16, C=8, T=512 -> 128 independent 512x512 DTW DPs.
// One block (128 threads / 4 warps) per pair; lane l owns 4 DP columns.
// Superstep = 4 rows x 4 cols; sigma = lane + 39*warp.
// R11: grouped supersteps (4/group), ONE combined sentinel check per group.
//   FIX vs R10: with IWS=39 the consumer's slot lag is 8 (t-8), not 0 --
//   each producer region now has an 8-slot BIG guard prefix and the consumer
//   pointer starts at logical slot -8. Producer lead = 2 groups -> check cold.
// BIG-fill handoff: fill carries are bit-exact BIG (1e30+c==1e30), warp0
//   polls 4 frozen BIG slots, drain garbage >= 0 and never consumed
//   (consumer's last slot == producer's last valid superstep, verified).

#define TT    512
#define IWS   39
#define SIGMX (31 + 3 * IWS)       // 148
#define NSS   (TT / 4 + SIGMX)     // 276 supersteps
#define NG    (NSS / 4)            // 69 groups
#define GUARD 8                    // slot lag for IWS=39
#define REG   (GUARD + NSS)        // per-producer region (guards + slots)
#define BIGF  1e30f

__device__ float        g_partials[128];
__device__ unsigned int g_counter = 0;

// One superstep: 4 rows (xq_) x 4 cols. hq_ = cross-warp lefts for lane 0.
#define SS(xq_, hq_, k_) do {                                                  \
    float L0 = __shfl_up_sync(0xffffffffu, c0, 1);                             \
    float L1 = __shfl_up_sync(0xffffffffu, c1, 1);                             \
    float L2 = __shfl_up_sync(0xffffffffu, c2, 1);                             \
    float L3 = __shfl_up_sync(0xffffffffu, c3, 1);                             \
    if (lane == 0) { L0 = hq_.x; L1 = hq_.y; L2 = hq_.z; L3 = hq_.w; }         \
    float m;                                                                   \
    m = fminf(up0, lprev); const float v00 = fabsf(xq_.x - y0) + fminf(L0,  m);\
    m = fminf(up1, up0 );  const float v01 = fabsf(xq_.x - y1) + fminf(v00, m);\
    m = fminf(up2, up1 );  const float v02 = fabsf(xq_.x - y2) + fminf(v01, m);\
    m = fminf(up3, up2 );  const float v03 = fabsf(xq_.x - y3) + fminf(v02, m);\
    m = fminf(v00, L0);    const float v10 = fabsf(xq_.y - y0) + fminf(L1,  m);\
    m = fminf(v01, v00);   const float v11 = fabsf(xq_.y - y1) + fminf(v10, m);\
    m = fminf(v02, v01);   const float v12 = fabsf(xq_.y - y2) + fminf(v11, m);\
    m = fminf(v03, v02);   const float v13 = fabsf(xq_.y - y3) + fminf(v12, m);\
    m = fminf(v10, L1);    const float v20 = fabsf(xq_.z - y0) + fminf(L2,  m);\
    m = fminf(v11, v10);   const float v21 = fabsf(xq_.z - y1) + fminf(v20, m);\
    m = fminf(v12, v11);   const float v22 = fabsf(xq_.z - y2) + fminf(v21, m);\
    m = fminf(v13, v12);   const float v23 = fabsf(xq_.z - y3) + fminf(v22, m);\
    m = fminf(v20, L2);    const float v30 = fabsf(xq_.w - y0) + fminf(L3,  m);\
    m = fminf(v21, v20);   const float v31 = fabsf(xq_.w - y1) + fminf(v30, m);\
    m = fminf(v22, v21);   const float v32 = fabsf(xq_.w - y2) + fminf(v31, m);\
    m = fminf(v23, v22);   const float v33 = fabsf(xq_.w - y3) + fminf(v32, m);\
    up0 = v30; up1 = v31; up2 = v32; up3 = v33; lprev = L3;                    \
    c0 = v03; c1 = v13; c2 = v23; c3 = v33;                                    \
    if (prod) qq[k_] = make_float4(c0, c1, c2, c3);                            \
} while (0)

// Cold path: volatile re-poll of one slot until its .w leaves sentinel.
#define FIXSLOT(h_, k_) do {                                                   \
    volatile float* vp = (volatile float*)(pp + (k_));                         \
    float w = vp[3];                                                           \
    while (w < 0.0f) { w = vp[3]; }                                            \
    (h_).x = vp[0]; (h_).y = vp[1]; (h_).z = vp[2]; (h_).w = w;                \
} while (0)

__global__ __launch_bounds__(128, 1)
void dtw_fused_kernel(const float* __restrict__ inputs,
                      const float* __restrict__ targets,
                      float* __restrict__ out) {
    const int p    = blockIdx.x;
    const float* x = inputs + p * TT;
    const int tid  = threadIdx.x;
    const int lane = tid & 31;
    const int warp = tid >> 5;
    const int sig  = lane + IWS * warp;

    // x rows as float4/superstep, zero-padded SIGMX on both sides.
    __shared__ float4 xsbuf[SIGMX + TT / 4 + SIGMX];      // 424 float4
    // handbuf: 4 frozen BIG slots (warp0) + 3 regions (8 BIG guards + NSS).
    __shared__ float4 handbuf[4 + 3 * REG];               // 856 float4

    {   // init smem (disjoint writes; one barrier below)
        float* xf = (float*)xsbuf;
        const int PRE = SIGMX * 4;                        // 592 floats
        for (int k = tid; k < PRE; k += 128) xf[k] = 0.0f;
        for (int k = tid; k < PRE; k += 128) xf[PRE + TT + k] = 0.0f;
        for (int k = tid; k < TT;  k += 128) xf[PRE + k] = x[k];
        float* hf = (float*)handbuf;
        for (int k = tid; k < (4 + 3 * REG) * 4; k += 128) hf[k] = -1.0f;
    }
    __syncthreads();
    {   // overwrite guard slots with BIG (warp0 block + 3 region prefixes)
        float* hf = (float*)handbuf;
        for (int k = tid; k < 16; k += 128) hf[k] = BIGF;                 // warp0
        for (int r = 0; r < 3; ++r)
            for (int k = tid; k < GUARD * 4; k += 128)
                hf[(4 + r * REG) * 4 + k] = BIGF;
    }

    const float4 yq = ((const float4*)(targets + p * TT))[tid];
    const float y0 = yq.x, y1 = yq.y, y2 = yq.z, y3 = yq.w;

    float up0 = BIGF, up1 = BIGF, up2 = BIGF, up3 = BIGF;
    float lprev = (tid == 0) ? 0.0f : BIGF;
    float c0 = BIGF, c1 = BIGF, c2 = BIGF, c3 = BIGF;

    const bool prod = (lane == 31 && warp < 3);
    // consumer base = guard start of previous warp's region (logical slot -8);
    // superstep t consumes logical slot t-8. warp0 stays on its BIG block.
    float4* pp = (warp > 0) ? (handbuf + 4 + (warp - 1) * REG) : handbuf;
    const int pinc = (warp > 0) ? 4 : 0;
    float4* qq = handbuf + 4 + warp * REG + GUARD;        // producer slot 0
    const float4* xp = xsbuf + SIGMX - sig;

    __syncthreads();

    for (int g = 0; g < NG; ++g) {
        // Burst-load this group's 4 handoff slots (slots 4g-8 .. 4g-5).
        float4 hq0 = pp[0], hq1 = pp[1], hq2 = pp[2], hq3 = pp[3];
        // ONE combined, warp-uniform sentinel check per group (cold:
        // producer wrote these slots two groups ago).
        if ((hq0.w < 0.0f) | (hq1.w < 0.0f) | (hq2.w < 0.0f) | (hq3.w < 0.0f)) {
            FIXSLOT(hq0, 0); FIXSLOT(hq1, 1); FIXSLOT(hq2, 2); FIXSLOT(hq3, 3);
        }

        const float4 xq0 = xp[0], xq1 = xp[1], xq2 = xp[2], xq3 = xp[3];

        SS(xq0, hq0, 0);
        SS(xq1, hq1, 1);
        SS(xq2, hq2, 2);
        SS(xq3, hq3, 3);

        pp += pinc; qq += 4; xp += 4;
    }

    // tid 127 (sig = 148): window [148, 275]; after loop c3 = dtw[T][T].
    if (tid == 127) {
        g_partials[p] = c3 * (1.0f / (float)TT);
        __threadfence();
        unsigned int old = atomicAdd(&g_counter, 1u);
        if (old == 127u) {
            volatile float* gp = g_partials;
            float sum = 0.0f;
            #pragma unroll 16
            for (int k = 0; k < 128; ++k) sum += gp[k];
            out[0] = sum * 0.125f;                       // (1/C) * sum_b
            *(volatile unsigned int*)&g_counter = 0;     // reset for replay
        }
    }
}

extern "C" void kernel_launch(void* const* d_in, const int* in_sizes, int n_in,
                              void* d_out, int out_size) {
    const float* inputs  = (const float*)d_in[0];
    const float* targets = (const float*)d_in[1];
    float* out = (float*)d_out;
    (void)in_sizes; (void)n_in; (void)out_size;

    dtw_fused_kernel<<<128, 128>>>(inputs, targets, out);
}